// round 2
// baseline (speedup 1.0000x reference)
#include <cuda_runtime.h>
#include <math.h>

#define B_    4
#define S_    512
#define D_    512
#define H_    8
#define DH_   64
#define MEM_  512
#define CMEM_ 128
#define KV_   1152
#define LLAT_ 256
#define FF_   2048
#define NL_   4

// ------------------------- scratch (device globals) -------------------------
__device__ float g_x   [B_*S_*D_];
__device__ float g_a   [B_*S_*D_];
__device__ float g_kv  [B_*KV_*D_];
__device__ float g_q   [B_*S_*D_];
__device__ float g_k   [B_*KV_*D_];
__device__ float g_v   [B_*KV_*D_];
__device__ float g_dots[B_*H_*S_*KV_];
__device__ float g_pd  [B_*H_*S_*KV_];
__device__ float g_ctx [B_*S_*D_];
__device__ float g_packw[ (4*D_) * D_ ];          // 2048 x 512
__device__ float g_newcm[B_*CMEM_*D_];
__device__ float g_kt  [B_*MEM_*D_];
__device__ float g_vt  [B_*MEM_*D_];
__device__ float g_kc  [B_*CMEM_*D_];
__device__ float g_vc  [B_*CMEM_*D_];
__device__ float g_dots2[B_*H_*S_*MEM_];          // also reused for src attn (L=256)
__device__ float g_dots3[B_*H_*S_*CMEM_];
__device__ float g_ctxt[B_*S_*D_];
__device__ float g_ctxc[B_*S_*D_];
__device__ float g_y   [B_*S_*D_];
__device__ float g_h1  [B_*S_*FF_];
__device__ float g_ff  [B_*S_*D_];
__device__ float g_loss[1];

// ------------------------------- GEMM --------------------------------------
// C[z] = alpha * A[z] @ op(B[z]) + bias, op = B^T if TB.
// z = blockIdx.z;  b = z / Hdiv, h = z % Hdiv ; per-(b,h) pointer offsets.
template<bool TB>
__global__ void __launch_bounds__(256) gemm_k(
    const float* __restrict__ A, const float* __restrict__ Bm,
    float* __restrict__ C, const float* __restrict__ bias,
    int M, int N, int K, int lda, int ldb, int ldc, float alpha,
    int Hdiv, long sAb, long sAh, long sBb, long sBh, long sCb, long sCh)
{
    int z  = blockIdx.z;
    int bi = z / Hdiv, hi = z - bi * Hdiv;
    A  += (long)bi*sAb + (long)hi*sAh;
    Bm += (long)bi*sBb + (long)hi*sBh;
    C  += (long)bi*sCb + (long)hi*sCh;

    __shared__ float As[16][64];
    __shared__ float Bs[16][64];

    const int t  = threadIdx.x;
    const int tx = t & 15, ty = t >> 4;
    const int m0 = blockIdx.y * 64, n0 = blockIdx.x * 64;

    float acc[4][4];
#pragma unroll
    for (int i = 0; i < 4; i++)
#pragma unroll
        for (int j = 0; j < 4; j++) acc[i][j] = 0.f;

    const int lrow  = t >> 2;          // 0..63
    const int lcol  = (t & 3) << 2;    // 0,4,8,12
    const int bnrow = t >> 4;          // 0..15
    const int bncol = (t & 15) << 2;   // 0..60

    for (int k0 = 0; k0 < K; k0 += 16) {
        { // A tile (BMxBK), K-contiguous float4
            int gm = m0 + lrow;
            float4 va = make_float4(0.f,0.f,0.f,0.f);
            if (gm < M) va = *reinterpret_cast<const float4*>(A + (long)gm*lda + k0 + lcol);
            As[lcol+0][lrow] = va.x; As[lcol+1][lrow] = va.y;
            As[lcol+2][lrow] = va.z; As[lcol+3][lrow] = va.w;
        }
        if (TB) {
            int gn = n0 + lrow;
            float4 vb = make_float4(0.f,0.f,0.f,0.f);
            if (gn < N) vb = *reinterpret_cast<const float4*>(Bm + (long)gn*ldb + k0 + lcol);
            Bs[lcol+0][lrow] = vb.x; Bs[lcol+1][lrow] = vb.y;
            Bs[lcol+2][lrow] = vb.z; Bs[lcol+3][lrow] = vb.w;
        } else {
            int gk = k0 + bnrow;
            int gn = n0 + bncol;
            float4 vb = make_float4(0.f,0.f,0.f,0.f);
            if (gn < N) vb = *reinterpret_cast<const float4*>(Bm + (long)gk*ldb + gn);
            *reinterpret_cast<float4*>(&Bs[bnrow][bncol]) = vb;
        }
        __syncthreads();
#pragma unroll
        for (int kk = 0; kk < 16; kk++) {
            float4 av = *reinterpret_cast<const float4*>(&As[kk][ty << 2]);
            float4 bv = *reinterpret_cast<const float4*>(&Bs[kk][tx << 2]);
            float ar[4] = {av.x, av.y, av.z, av.w};
            float br[4] = {bv.x, bv.y, bv.z, bv.w};
#pragma unroll
            for (int i = 0; i < 4; i++)
#pragma unroll
                for (int j = 0; j < 4; j++) acc[i][j] = fmaf(ar[i], br[j], acc[i][j]);
        }
        __syncthreads();
    }
#pragma unroll
    for (int i = 0; i < 4; i++) {
        int gm = m0 + (ty << 2) + i;
        if (gm >= M) continue;
#pragma unroll
        for (int j = 0; j < 4; j++) {
            int gn = n0 + (tx << 2) + j;
            if (gn >= N) continue;
            float v = alpha * acc[i][j];
            if (bias) v += bias[gn];
            C[(long)gm*ldc + gn] = v;
        }
    }
}

// ------------------------- elementwise / reduction kernels ------------------
__global__ void embed_k(const int* __restrict__ trg, const float* __restrict__ embed)
{
    int idx = blockIdx.x * blockDim.x + threadIdx.x;
    if (idx >= B_*S_*D_) return;
    int row = idx / D_;
    g_x[idx] = embed[(long)trg[row]*D_ + (idx % D_)];
}

__global__ void concat_kv_k(const float* __restrict__ cm, const float* __restrict__ m)
{
    int idx = blockIdx.x * blockDim.x + threadIdx.x;
    if (idx >= B_*KV_*D_) return;
    int d = idx % D_;
    int j = (idx / D_) % KV_;
    int b = idx / (D_*KV_);
    float v;
    if (j < CMEM_)             v = cm [((long)b*CMEM_ + j)*D_ + d];
    else if (j < CMEM_ + MEM_) v = m  [((long)b*MEM_ + (j - CMEM_))*D_ + d];
    else                       v = g_x[((long)b*S_  + (j - CMEM_ - MEM_))*D_ + d];
    g_kv[idx] = v;
}

// dots += shifted(pos_dots)
__global__ void combine_pos_k()
{
    int idx = blockIdx.x * blockDim.x + threadIdx.x;
    if (idx >= B_*H_*S_*KV_) return;
    int k = idx % KV_;
    int q = (idx / KV_) % S_;
    int p = k - q + (S_ - 1);
    if (p < KV_) {
        int bh = idx / (KV_*S_);
        g_dots[idx] += g_pd[((long)bh*S_ + q)*KV_ + p];
    }
}

__global__ void softmax_k(float* __restrict__ d, int L)
{
    long row = blockIdx.x;
    float* p = d + row * (long)L;
    __shared__ float red[256];
    int t = threadIdx.x;
    float m = -1e30f;
    for (int i = t; i < L; i += 256) m = fmaxf(m, p[i]);
    red[t] = m; __syncthreads();
    for (int st = 128; st > 0; st >>= 1) { if (t < st) red[t] = fmaxf(red[t], red[t+st]); __syncthreads(); }
    m = red[0]; __syncthreads();
    float s = 0.f;
    for (int i = t; i < L; i += 256) { float e = expf(p[i] - m); p[i] = e; s += e; }
    red[t] = s; __syncthreads();
    for (int st = 128; st > 0; st >>= 1) { if (t < st) red[t] += red[t+st]; __syncthreads(); }
    float inv = 1.f / red[0];
    for (int i = t; i < L; i += 256) p[i] *= inv;
}

// LayerNorm over D_ (optionally with residual 'res' added first). 256 threads/row.
__global__ void ln_k(const float* __restrict__ in, const float* __restrict__ res,
                     float* __restrict__ out, const float* __restrict__ g,
                     const float* __restrict__ bta)
{
    long row = blockIdx.x;
    const float* p = in + row * D_;
    int t = threadIdx.x;
    float v0 = p[t]       + (res ? res[row*D_ + t]       : 0.f);
    float v1 = p[t + 256] + (res ? res[row*D_ + t + 256] : 0.f);
    __shared__ float s1[256], s2[256];
    s1[t] = v0 + v1; s2[t] = v0*v0 + v1*v1;
    __syncthreads();
    for (int st = 128; st > 0; st >>= 1) { if (t < st) { s1[t] += s1[t+st]; s2[t] += s2[t+st]; } __syncthreads(); }
    float mu  = s1[0] * (1.f / D_);
    float var = s2[0] * (1.f / D_) - mu*mu;
    float inv = rsqrtf(var + 1e-5f);
    out[row*D_ + t]       = (v0 - mu) * inv * g[t]       + bta[t];
    out[row*D_ + t + 256] = (v1 - mu) * inv * g[t + 256] + bta[t + 256];
}

// pack conv_w (Dout=512, D=512, R=4) -> (K=2048 rows [r*D+d], N=512 cols [o])
__global__ void pack_convw_k(const float* __restrict__ w)
{
    int idx = blockIdx.x * blockDim.x + threadIdx.x;
    if (idx >= (4*D_)*D_) return;
    int o = idx % D_;
    int kap = idx / D_;
    int r = kap / D_, d = kap % D_;
    g_packw[(long)kap*D_ + o] = w[(long)o*(D_*4) + d*4 + r];
}

__global__ void gelu_k(float* __restrict__ p, int n)
{
    int idx = blockIdx.x * blockDim.x + threadIdx.x;
    if (idx >= n) return;
    float v = p[idx];
    p[idx] = 0.5f * v * (1.f + erff(v * 0.70710678118654752f));
}

__global__ void add_k(const float* __restrict__ a, const float* __restrict__ b,
                      float* __restrict__ out, int n)
{
    int idx = blockIdx.x * blockDim.x + threadIdx.x;
    if (idx >= n) return;
    out[idx] = a[idx] + b[idx];
}

__global__ void zero_loss_k() { if (threadIdx.x == 0 && blockIdx.x == 0) g_loss[0] = 0.f; }

__global__ void sse_k(const float* __restrict__ a, const float* __restrict__ b, int n)
{
    __shared__ float red[256];
    int t = threadIdx.x;
    float s = 0.f;
    for (int i = blockIdx.x * 256 + t; i < n; i += gridDim.x * 256) {
        float d = a[i] - b[i];
        s += d * d;
    }
    red[t] = s; __syncthreads();
    for (int st = 128; st > 0; st >>= 1) { if (t < st) red[t] += red[t+st]; __syncthreads(); }
    if (t == 0) atomicAdd(&g_loss[0], red[0]);
}

__global__ void finalize_k(float* __restrict__ out, int out_size)
{
    int idx = blockIdx.x * blockDim.x + threadIdx.x;
    if (idx >= out_size) return;
    const int n = B_*S_*D_;
    if (idx < n) out[idx] = g_x[idx];
    else         out[idx] = g_loss[0] * (1.f / ((float)n * (float)NL_));
}

// ------------------------------- host driver --------------------------------
static void gemm(bool tb, const float* A, const float* Bm, float* C, const float* bias,
                 int M, int N, int K, int lda, int ldb, int ldc, float alpha,
                 int batch = 1, int Hdiv = 1,
                 long sAb = 0, long sAh = 0, long sBb = 0, long sBh = 0,
                 long sCb = 0, long sCh = 0)
{
    dim3 grid((N + 63) / 64, (M + 63) / 64, batch);
    if (tb)
        gemm_k<true><<<grid, 256>>>(A, Bm, C, bias, M, N, K, lda, ldb, ldc, alpha,
                                    Hdiv, sAb, sAh, sBb, sBh, sCb, sCh);
    else
        gemm_k<false><<<grid, 256>>>(A, Bm, C, bias, M, N, K, lda, ldb, ldc, alpha,
                                     Hdiv, sAb, sAh, sBb, sBh, sCb, sCh);
}

static float* dptr(const void* sym) { void* p = nullptr; cudaGetSymbolAddress(&p, sym); return (float*)p; }

extern "C" void kernel_launch(void* const* d_in, const int* in_sizes, int n_in,
                              void* d_out, int out_size)
{
    const int*   trg     = (const int*)  d_in[0];
    // d_in[1] trg_mask, d_in[2] src_mask : all True -> no-ops
    const float* latent  = (const float*)d_in[3];
    const float* mems    = (const float*)d_in[4];
    const float* cmems   = (const float*)d_in[5];
    const float* pos_emb = (const float*)d_in[6];
    const float* embed   = (const float*)d_in[7];
    const float* W_self  = (const float*)d_in[8];
    const float* ln1_g   = (const float*)d_in[9];
    const float* ln1_b   = (const float*)d_in[10];
    const float* conv_w  = (const float*)d_in[11];
    const float* conv_b  = (const float*)d_in[12];
    const float* W_src   = (const float*)d_in[13];
    const float* ln2_g   = (const float*)d_in[14];
    const float* ln2_b   = (const float*)d_in[15];
    const float* w1      = (const float*)d_in[16];
    const float* b1      = (const float*)d_in[17];
    const float* w2      = (const float*)d_in[18];
    const float* b2      = (const float*)d_in[19];

    float* px    = dptr(g_x);     float* pa    = dptr(g_a);
    float* pkv   = dptr(g_kv);    float* pq    = dptr(g_q);
    float* pk    = dptr(g_k);     float* pv    = dptr(g_v);
    float* pdots = dptr(g_dots);  float* ppd   = dptr(g_pd);
    float* pctx  = dptr(g_ctx);   float* ppackw= dptr(g_packw);
    float* pnewcm= dptr(g_newcm); float* pkt   = dptr(g_kt);
    float* pvt   = dptr(g_vt);    float* pkc   = dptr(g_kc);
    float* pvc   = dptr(g_vc);    float* pd2   = dptr(g_dots2);
    float* pd3   = dptr(g_dots3); float* pctxt = dptr(g_ctxt);
    float* pctxc = dptr(g_ctxc);  float* py    = dptr(g_y);
    float* ph1   = dptr(g_h1);    float* pff   = dptr(g_ff);

    const int DD = D_ * D_;
    const int NX = B_*S_*D_;

    embed_k<<<(NX + 255)/256, 256>>>(trg, embed);
    zero_loss_k<<<1, 32>>>();

    for (int i = 0; i < NL_; i++) {
        const float* Wq = W_self + (long)i*4*DD;
        const float* Wk = Wq + DD;
        const float* Wv = Wq + 2*DD;
        const float* Wo = Wq + 3*DD;
        const float* Ws0 = W_src + (long)i*4*DD;
        const float* Ws1 = Ws0 + DD;
        const float* Ws2 = Ws0 + 2*DD;
        const float* Ws3 = Ws0 + 3*DD;
        const float* mems_i  = mems  + (long)i*B_*MEM_*D_;
        const float* cmems_i = cmems + (long)i*B_*CMEM_*D_;
        const float* convw_i = conv_w + (long)i*DD*4;
        const float* convb_i = conv_b + (long)i*D_;
        const float* w1_i = w1 + (long)i*D_*FF_;
        const float* b1_i = b1 + (long)i*FF_;
        const float* w2_i = w2 + (long)i*FF_*D_;
        const float* b2_i = b2 + (long)i*D_;

        // ---- self attention over kv = [cmem, mem, x] ----
        concat_kv_k<<<(B_*KV_*D_ + 255)/256, 256>>>(cmems_i, mems_i);
        gemm(false, px,  Wq, pq, nullptr, B_*S_,  D_, D_, D_, D_, D_, 1.f);
        gemm(false, pkv, Wk, pk, nullptr, B_*KV_, D_, D_, D_, D_, D_, 1.f);
        gemm(false, pkv, Wv, pv, nullptr, B_*KV_, D_, D_, D_, D_, D_, 1.f);
        // dots = 0.125 * Q K^T   (batched over b,h)
        gemm(true, pq, pk, pdots, nullptr, S_, KV_, DH_, D_, D_, KV_, 0.125f,
             B_*H_, H_, (long)S_*D_, 64, (long)KV_*D_, 64, (long)H_*S_*KV_, (long)S_*KV_);
        // pos dots = 8 * Q pos^T
        gemm(true, pq, pos_emb, ppd, nullptr, S_, KV_, DH_, D_, DH_, KV_, 8.f,
             B_*H_, H_, (long)S_*D_, 64, 0, (long)KV_*DH_, (long)H_*S_*KV_, (long)S_*KV_);
        combine_pos_k<<<(B_*H_*S_*KV_ + 255)/256, 256>>>();
        softmax_k<<<B_*H_*S_, 256>>>(pdots, KV_);
        // ctx = attn @ V
        gemm(false, pdots, pv, pctx, nullptr, S_, DH_, KV_, KV_, D_, D_, 1.f,
             B_*H_, H_, (long)H_*S_*KV_, (long)S_*KV_, (long)KV_*D_, 64, (long)S_*D_, 64);
        gemm(false, pctx, Wo, pa, nullptr, B_*S_, D_, D_, D_, D_, D_, 1.f);
        // x = LN(a + x)
        ln_k<<<B_*S_, 256>>>(pa, px, px, ln1_g + (long)i*D_, ln1_b + (long)i*D_);

        // ---- conv compress ----
        pack_convw_k<<<((4*D_)*D_ + 255)/256, 256>>>(convw_i);
        gemm(false, mems_i, ppackw, pnewcm, convb_i, B_*CMEM_, D_, 4*D_, 4*D_, D_, D_, 1.f);

        // ---- reconstruction attentions (loss) ----
        gemm(false, px, Wq, pq, nullptr, B_*S_, D_, D_, D_, D_, D_, 1.f);
        // target: attend over old_mem
        gemm(false, mems_i, Wk, pkt, nullptr, B_*MEM_, D_, D_, D_, D_, D_, 1.f);
        gemm(false, mems_i, Wv, pvt, nullptr, B_*MEM_, D_, D_, D_, D_, D_, 1.f);
        gemm(true, pq, pkt, pd2, nullptr, S_, MEM_, DH_, D_, D_, MEM_, 0.125f,
             B_*H_, H_, (long)S_*D_, 64, (long)MEM_*D_, 64, (long)H_*S_*MEM_, (long)S_*MEM_);
        softmax_k<<<B_*H_*S_, 256>>>(pd2, MEM_);
        gemm(false, pd2, pvt, pctxt, nullptr, S_, DH_, MEM_, MEM_, D_, D_, 1.f,
             B_*H_, H_, (long)H_*S_*MEM_, (long)S_*MEM_, (long)MEM_*D_, 64, (long)S_*D_, 64);
        // compressed: attend over new_cm
        gemm(false, pnewcm, Wk, pkc, nullptr, B_*CMEM_, D_, D_, D_, D_, D_, 1.f);
        gemm(false, pnewcm, Wv, pvc, nullptr, B_*CMEM_, D_, D_, D_, D_, D_, 1.f);
        gemm(true, pq, pkc, pd3, nullptr, S_, CMEM_, DH_, D_, D_, CMEM_, 0.125f,
             B_*H_, H_, (long)S_*D_, 64, (long)CMEM_*D_, 64, (long)H_*S_*CMEM_, (long)S_*CMEM_);
        softmax_k<<<B_*H_*S_, 256>>>(pd3, CMEM_);
        gemm(false, pd3, pvc, pctxc, nullptr, S_, DH_, CMEM_, CMEM_, D_, D_, 1.f,
             B_*H_, H_, (long)H_*S_*CMEM_, (long)S_*CMEM_, (long)CMEM_*D_, 64, (long)S_*D_, 64);
        sse_k<<<1024, 256>>>(pctxc, pctxt, NX);

        // ---- cross attention to latent (output REPLACES x) ----
        gemm(false, px,     Ws0, pq,  nullptr, B_*S_,    D_, D_, D_, D_, D_, 1.f);
        gemm(false, latent, Ws1, pkt, nullptr, B_*LLAT_, D_, D_, D_, D_, D_, 1.f);
        gemm(false, latent, Ws2, pvt, nullptr, B_*LLAT_, D_, D_, D_, D_, D_, 1.f);
        gemm(true, pq, pkt, pd2, nullptr, S_, LLAT_, DH_, D_, D_, LLAT_, 0.125f,
             B_*H_, H_, (long)S_*D_, 64, (long)LLAT_*D_, 64, (long)H_*S_*LLAT_, (long)S_*LLAT_);
        softmax_k<<<B_*H_*S_, 256>>>(pd2, LLAT_);
        gemm(false, pd2, pvt, pctx, nullptr, S_, DH_, LLAT_, LLAT_, D_, D_, 1.f,
             B_*H_, H_, (long)H_*S_*LLAT_, (long)S_*LLAT_, (long)LLAT_*D_, 64, (long)S_*D_, 64);
        gemm(false, pctx, Ws3, pa, nullptr, B_*S_, D_, D_, D_, D_, D_, 1.f);

        // ---- FFN: x = a + gelu(LN(a) @ w1 + b1) @ w2 + b2 ----
        ln_k<<<B_*S_, 256>>>(pa, nullptr, py, ln2_g + (long)i*D_, ln2_b + (long)i*D_);
        gemm(false, py, w1_i, ph1, b1_i, B_*S_, FF_, D_, D_, FF_, FF_, 1.f);
        gelu_k<<<(B_*S_*FF_ + 255)/256, 256>>>(ph1, B_*S_*FF_);
        gemm(false, ph1, w2_i, pff, b2_i, B_*S_, D_, FF_, FF_, D_, D_, 1.f);
        add_k<<<(NX + 255)/256, 256>>>(pa, pff, px, NX);
    }

    finalize_k<<<(out_size + 255)/256, 256>>>((float*)d_out, out_size);
}

// round 3
// speedup vs baseline: 1.0834x; 1.0834x over previous
#include <cuda_runtime.h>
#include <math.h>

#define B_    4
#define S_    512
#define D_    512
#define H_    8
#define DH_   64
#define MEM_  512
#define CMEM_ 128
#define KV_   1152
#define LLAT_ 256
#define FF_   2048
#define NL_   4

// ------------------------- scratch (device globals) -------------------------
__device__ float g_x   [B_*S_*D_];
__device__ float g_a   [B_*S_*D_];
__device__ float g_kv  [B_*KV_*D_];
__device__ float g_q   [B_*S_*D_];
__device__ float g_kvp [2*B_*KV_*D_];     // K then V (self attn)
__device__ float g_dots[B_*H_*S_*KV_];
__device__ float g_pd  [B_*H_*S_*KV_];
__device__ float g_ctx [B_*S_*D_];
__device__ float g_packw[(4*D_)*D_];      // 2048 x 512
__device__ float g_newcm[B_*CMEM_*D_];
__device__ float g_tb  [2*B_*MEM_*D_];    // kt then vt (recon mem / cross latent)
__device__ float g_cb  [2*B_*CMEM_*D_];   // kc then vc
__device__ float g_d2  [B_*H_*S_*MEM_];
__device__ float g_d3  [B_*H_*S_*CMEM_];
__device__ float g_ctxt[B_*S_*D_];
__device__ float g_ctxc[B_*S_*D_];
__device__ float g_y   [B_*S_*D_];
__device__ float g_h1  [B_*S_*FF_];
__device__ float g_loss[1];

// --------------------------- fast SGEMM -------------------------------------
// C = alpha * A @ op(B) [+ bias] [+ Res] [GELU], op = B^T if TB.
// Requires: M % 128 == 0, N % BN == 0, K % 16 == 0, lda/ldb/ldc % 4 == 0,
// all base pointers 16B aligned. Batched via blockIdx.z (bi = z/Hdiv, hi = z%Hdiv).
template<int BN, bool TB, bool GELU>
__global__ void __launch_bounds__(256, 2) gemm_f(
    const float* __restrict__ A, const float* __restrict__ Bm,
    float* __restrict__ C, const float* __restrict__ bias,
    const float* __restrict__ Res,
    int K, int lda, int ldb, int ldc, float alpha,
    int Hdiv, long sAb, long sAh, long sBb, long sBh, long sCb, long sCh)
{
    constexpr int BK = 16;
    constexpr int NB = BN / 64;             // 2 (BN=128) or 1 (BN=64)

    const int z  = blockIdx.z;
    const int bi = z / Hdiv, hi = z - bi * Hdiv;
    A  += (long)bi*sAb + (long)hi*sAh;
    Bm += (long)bi*sBb + (long)hi*sBh;
    C  += (long)bi*sCb + (long)hi*sCh;

    const int m0 = blockIdx.y * 128;
    const int n0 = blockIdx.x * BN;

    __shared__ float As[2][BK][128];
    __shared__ float Bs[2][BK][BN];

    const int t  = threadIdx.x;
    const int tx = t & 15, ty = t >> 4;
    const int ar = t >> 2;                  // 0..63
    const int ac = (t & 3) << 2;            // 0,4,8,12

    float4 pa0, pa1, pb0, pb1;

    float acc[2][NB][16];
#pragma unroll
    for (int im = 0; im < 2; im++)
#pragma unroll
        for (int in = 0; in < NB; in++)
#pragma unroll
            for (int e = 0; e < 16; e++) acc[im][in][e] = 0.f;

    const int nt = K >> 4;

    // ---- load tile 0 ----
    {
        const int k0 = 0;
        pa0 = *(const float4*)(A + (long)(m0 + ar     )*lda + k0 + ac);
        pa1 = *(const float4*)(A + (long)(m0 + ar + 64)*lda + k0 + ac);
        if (TB) {
            pb0 = *(const float4*)(Bm + (long)(n0 + ar)*ldb + k0 + ac);
            if (BN == 128)
                pb1 = *(const float4*)(Bm + (long)(n0 + ar + 64)*ldb + k0 + ac);
        } else {
            if (BN == 128) {
                pb0 = *(const float4*)(Bm + (long)(k0 + (t>>5)    )*ldb + n0 + ((t&31)<<2));
                pb1 = *(const float4*)(Bm + (long)(k0 + (t>>5) + 8)*ldb + n0 + ((t&31)<<2));
            } else {
                pb0 = *(const float4*)(Bm + (long)(k0 + (t>>4))*ldb + n0 + ((t&15)<<2));
            }
        }
        As[0][ac+0][ar] = pa0.x; As[0][ac+1][ar] = pa0.y;
        As[0][ac+2][ar] = pa0.z; As[0][ac+3][ar] = pa0.w;
        As[0][ac+0][ar+64] = pa1.x; As[0][ac+1][ar+64] = pa1.y;
        As[0][ac+2][ar+64] = pa1.z; As[0][ac+3][ar+64] = pa1.w;
        if (TB) {
            Bs[0][ac+0][ar] = pb0.x; Bs[0][ac+1][ar] = pb0.y;
            Bs[0][ac+2][ar] = pb0.z; Bs[0][ac+3][ar] = pb0.w;
            if (BN == 128) {
                Bs[0][ac+0][ar+64] = pb1.x; Bs[0][ac+1][ar+64] = pb1.y;
                Bs[0][ac+2][ar+64] = pb1.z; Bs[0][ac+3][ar+64] = pb1.w;
            }
        } else {
            if (BN == 128) {
                *(float4*)&Bs[0][(t>>5)    ][(t&31)<<2] = pb0;
                *(float4*)&Bs[0][(t>>5) + 8][(t&31)<<2] = pb1;
            } else {
                *(float4*)&Bs[0][t>>4][(t&15)<<2] = pb0;
            }
        }
    }
    __syncthreads();

    for (int tt = 0; tt < nt; tt++) {
        const int buf = tt & 1;
        const int nk0 = (tt + 1) << 4;
        if (tt + 1 < nt) {
            pa0 = *(const float4*)(A + (long)(m0 + ar     )*lda + nk0 + ac);
            pa1 = *(const float4*)(A + (long)(m0 + ar + 64)*lda + nk0 + ac);
            if (TB) {
                pb0 = *(const float4*)(Bm + (long)(n0 + ar)*ldb + nk0 + ac);
                if (BN == 128)
                    pb1 = *(const float4*)(Bm + (long)(n0 + ar + 64)*ldb + nk0 + ac);
            } else {
                if (BN == 128) {
                    pb0 = *(const float4*)(Bm + (long)(nk0 + (t>>5)    )*ldb + n0 + ((t&31)<<2));
                    pb1 = *(const float4*)(Bm + (long)(nk0 + (t>>5) + 8)*ldb + n0 + ((t&31)<<2));
                } else {
                    pb0 = *(const float4*)(Bm + (long)(nk0 + (t>>4))*ldb + n0 + ((t&15)<<2));
                }
            }
        }

#pragma unroll
        for (int kk = 0; kk < BK; kk++) {
            float4 a0 = *(const float4*)&As[buf][kk][ty<<2];
            float4 a1 = *(const float4*)&As[buf][kk][(ty<<2) + 64];
            float am[2][4] = {{a0.x,a0.y,a0.z,a0.w},{a1.x,a1.y,a1.z,a1.w}};
            float bn[2][4];
            {
                float4 b0 = *(const float4*)&Bs[buf][kk][tx<<2];
                bn[0][0]=b0.x; bn[0][1]=b0.y; bn[0][2]=b0.z; bn[0][3]=b0.w;
                if (NB == 2) {
                    float4 b1 = *(const float4*)&Bs[buf][kk][(tx<<2) + 64];
                    bn[1][0]=b1.x; bn[1][1]=b1.y; bn[1][2]=b1.z; bn[1][3]=b1.w;
                }
            }
#pragma unroll
            for (int im = 0; im < 2; im++)
#pragma unroll
                for (int in = 0; in < NB; in++)
#pragma unroll
                    for (int i = 0; i < 4; i++)
#pragma unroll
                        for (int j = 0; j < 4; j++)
                            acc[im][in][i*4+j] = fmaf(am[im][i], bn[in][j], acc[im][in][i*4+j]);
        }

        if (tt + 1 < nt) {
            const int nb = (tt + 1) & 1;
            As[nb][ac+0][ar] = pa0.x; As[nb][ac+1][ar] = pa0.y;
            As[nb][ac+2][ar] = pa0.z; As[nb][ac+3][ar] = pa0.w;
            As[nb][ac+0][ar+64] = pa1.x; As[nb][ac+1][ar+64] = pa1.y;
            As[nb][ac+2][ar+64] = pa1.z; As[nb][ac+3][ar+64] = pa1.w;
            if (TB) {
                Bs[nb][ac+0][ar] = pb0.x; Bs[nb][ac+1][ar] = pb0.y;
                Bs[nb][ac+2][ar] = pb0.z; Bs[nb][ac+3][ar] = pb0.w;
                if (BN == 128) {
                    Bs[nb][ac+0][ar+64] = pb1.x; Bs[nb][ac+1][ar+64] = pb1.y;
                    Bs[nb][ac+2][ar+64] = pb1.z; Bs[nb][ac+3][ar+64] = pb1.w;
                }
            } else {
                if (BN == 128) {
                    *(float4*)&Bs[nb][(t>>5)    ][(t&31)<<2] = pb0;
                    *(float4*)&Bs[nb][(t>>5) + 8][(t&31)<<2] = pb1;
                } else {
                    *(float4*)&Bs[nb][t>>4][(t&15)<<2] = pb0;
                }
            }
            __syncthreads();
        }
    }

    // ---- epilogue ----
#pragma unroll
    for (int im = 0; im < 2; im++) {
#pragma unroll
        for (int i = 0; i < 4; i++) {
            const int gm = m0 + im*64 + (ty<<2) + i;
            float* crow = C + (long)gm*ldc;
            const float* rrow = Res ? (Res + (long)gm*ldc) : nullptr;
#pragma unroll
            for (int in = 0; in < NB; in++) {
                const int gn = n0 + in*64 + (tx<<2);
                float4 o;
                o.x = alpha*acc[im][in][i*4+0];
                o.y = alpha*acc[im][in][i*4+1];
                o.z = alpha*acc[im][in][i*4+2];
                o.w = alpha*acc[im][in][i*4+3];
                if (bias) {
                    float4 bv = *(const float4*)&bias[gn];
                    o.x += bv.x; o.y += bv.y; o.z += bv.z; o.w += bv.w;
                }
                if (GELU) {
                    o.x = 0.5f*o.x*(1.f + erff(o.x*0.70710678118654752f));
                    o.y = 0.5f*o.y*(1.f + erff(o.y*0.70710678118654752f));
                    o.z = 0.5f*o.z*(1.f + erff(o.z*0.70710678118654752f));
                    o.w = 0.5f*o.w*(1.f + erff(o.w*0.70710678118654752f));
                }
                if (rrow) {
                    float4 rv = *(const float4*)&rrow[gn];
                    o.x += rv.x; o.y += rv.y; o.z += rv.z; o.w += rv.w;
                }
                *(float4*)&crow[gn] = o;
            }
        }
    }
}

// ------------------------- elementwise / reduction kernels ------------------
__global__ void embed_k(const int* __restrict__ trg, const float* __restrict__ embed)
{
    int idx = blockIdx.x * blockDim.x + threadIdx.x;
    if (idx >= B_*S_*D_) return;
    int row = idx / D_;
    g_x[idx] = embed[(long)trg[row]*D_ + (idx % D_)];
}

__global__ void concat_kv_k(const float* __restrict__ cm, const float* __restrict__ m)
{
    int idx = blockIdx.x * blockDim.x + threadIdx.x;
    if (idx >= B_*KV_*D_) return;
    int d = idx % D_;
    int j = (idx / D_) % KV_;
    int b = idx / (D_*KV_);
    float v;
    if (j < CMEM_)             v = cm [((long)b*CMEM_ + j)*D_ + d];
    else if (j < CMEM_ + MEM_) v = m  [((long)b*MEM_ + (j - CMEM_))*D_ + d];
    else                       v = g_x[((long)b*S_  + (j - CMEM_ - MEM_))*D_ + d];
    g_kv[idx] = v;
}

// softmax over KV with fused relative-position shift add:
// val[k] = dots[k] + (k - q + S - 1 < KV ? pd[k - q + S - 1] : 0)
__global__ void softmax_pos_k()
{
    const long row = blockIdx.x;                 // bh*S + q
    const int  q   = (int)(row % S_);
    float* dp = g_dots + row * (long)KV_;
    const float* pp = g_pd + row * (long)KV_;
    const int t = threadIdx.x;

    float v[5];
    float m = -1e30f;
#pragma unroll
    for (int r = 0; r < 5; r++) {
        int i = t + 256*r;
        if (i < KV_) {
            float val = dp[i];
            int p = i - q + (S_ - 1);
            if (p < KV_) val += pp[p];
            v[r] = val;
            m = fmaxf(m, val);
        } else v[r] = -1e30f;
    }
    __shared__ float red[256];
    red[t] = m; __syncthreads();
    for (int st = 128; st > 0; st >>= 1) { if (t < st) red[t] = fmaxf(red[t], red[t+st]); __syncthreads(); }
    m = red[0]; __syncthreads();
    float s = 0.f;
#pragma unroll
    for (int r = 0; r < 5; r++) {
        int i = t + 256*r;
        if (i < KV_) { v[r] = expf(v[r] - m); s += v[r]; }
    }
    red[t] = s; __syncthreads();
    for (int st = 128; st > 0; st >>= 1) { if (t < st) red[t] += red[t+st]; __syncthreads(); }
    float inv = 1.f / red[0];
#pragma unroll
    for (int r = 0; r < 5; r++) {
        int i = t + 256*r;
        if (i < KV_) dp[i] = v[r] * inv;
    }
}

__global__ void softmax_k(float* __restrict__ d, int L)
{
    long row = blockIdx.x;
    float* p = d + row * (long)L;
    const int t = threadIdx.x;
    float v[5];
    float m = -1e30f;
    const int nr = (L + 255) >> 8;
    for (int r = 0; r < nr; r++) {
        int i = t + 256*r;
        v[r] = (i < L) ? p[i] : -1e30f;
        m = fmaxf(m, v[r]);
    }
    __shared__ float red[256];
    red[t] = m; __syncthreads();
    for (int st = 128; st > 0; st >>= 1) { if (t < st) red[t] = fmaxf(red[t], red[t+st]); __syncthreads(); }
    m = red[0]; __syncthreads();
    float s = 0.f;
    for (int r = 0; r < nr; r++) {
        int i = t + 256*r;
        if (i < L) { v[r] = expf(v[r] - m); s += v[r]; }
    }
    red[t] = s; __syncthreads();
    for (int st = 128; st > 0; st >>= 1) { if (t < st) red[t] += red[t+st]; __syncthreads(); }
    float inv = 1.f / red[0];
    for (int r = 0; r < nr; r++) {
        int i = t + 256*r;
        if (i < L) p[i] = v[r] * inv;
    }
}

__global__ void ln_k(const float* __restrict__ in, const float* __restrict__ res,
                     float* __restrict__ out, const float* __restrict__ g,
                     const float* __restrict__ bta)
{
    long row = blockIdx.x;
    const float* p = in + row * D_;
    int t = threadIdx.x;
    float v0 = p[t]       + (res ? res[row*D_ + t]       : 0.f);
    float v1 = p[t + 256] + (res ? res[row*D_ + t + 256] : 0.f);
    __shared__ float s1[256], s2[256];
    s1[t] = v0 + v1; s2[t] = v0*v0 + v1*v1;
    __syncthreads();
    for (int st = 128; st > 0; st >>= 1) { if (t < st) { s1[t] += s1[t+st]; s2[t] += s2[t+st]; } __syncthreads(); }
    float mu  = s1[0] * (1.f / D_);
    float var = s2[0] * (1.f / D_) - mu*mu;
    float inv = rsqrtf(var + 1e-5f);
    out[row*D_ + t]       = (v0 - mu) * inv * g[t]       + bta[t];
    out[row*D_ + t + 256] = (v1 - mu) * inv * g[t + 256] + bta[t + 256];
}

__global__ void pack_convw_k(const float* __restrict__ w)
{
    int idx = blockIdx.x * blockDim.x + threadIdx.x;
    if (idx >= (4*D_)*D_) return;
    int o = idx % D_;
    int kap = idx / D_;
    int r = kap / D_, d = kap % D_;
    g_packw[(long)kap*D_ + o] = w[(long)o*(D_*4) + d*4 + r];
}

__global__ void zero_loss_k() { if (threadIdx.x == 0 && blockIdx.x == 0) g_loss[0] = 0.f; }

__global__ void sse_k(const float* __restrict__ a, const float* __restrict__ b, int n)
{
    __shared__ float red[256];
    int t = threadIdx.x;
    float s = 0.f;
    for (int i = blockIdx.x * 256 + t; i < n; i += gridDim.x * 256) {
        float d = a[i] - b[i];
        s += d * d;
    }
    red[t] = s; __syncthreads();
    for (int st = 128; st > 0; st >>= 1) { if (t < st) red[t] += red[t+st]; __syncthreads(); }
    if (t == 0) atomicAdd(&g_loss[0], red[0]);
}

__global__ void finalize_k(float* __restrict__ out, int out_size)
{
    int idx = blockIdx.x * blockDim.x + threadIdx.x;
    if (idx >= out_size) return;
    const int n = B_*S_*D_;
    if (idx < n) out[idx] = g_x[idx];
    else         out[idx] = g_loss[0] * (1.f / ((float)n * (float)NL_));
}

// ------------------------------- host driver --------------------------------
static void gF(bool tb, int bn, bool gelu,
               const float* A, const float* Bm, float* C, const float* bias,
               const float* Res, int M, int N, int K,
               int lda, int ldb, int ldc, float alpha,
               int batch = 1, int Hdiv = 1,
               long sAb = 0, long sAh = 0, long sBb = 0, long sBh = 0,
               long sCb = 0, long sCh = 0)
{
    dim3 g(N / bn, M / 128, batch);
    if (bn == 64)
        gemm_f<64,false,false><<<g,256>>>(A,Bm,C,bias,Res,K,lda,ldb,ldc,alpha,Hdiv,sAb,sAh,sBb,sBh,sCb,sCh);
    else if (tb)
        gemm_f<128,true,false><<<g,256>>>(A,Bm,C,bias,Res,K,lda,ldb,ldc,alpha,Hdiv,sAb,sAh,sBb,sBh,sCb,sCh);
    else if (gelu)
        gemm_f<128,false,true><<<g,256>>>(A,Bm,C,bias,Res,K,lda,ldb,ldc,alpha,Hdiv,sAb,sAh,sBb,sBh,sCb,sCh);
    else
        gemm_f<128,false,false><<<g,256>>>(A,Bm,C,bias,Res,K,lda,ldb,ldc,alpha,Hdiv,sAb,sAh,sBb,sBh,sCb,sCh);
}

static float* dptr(const void* sym) { void* p = nullptr; cudaGetSymbolAddress(&p, sym); return (float*)p; }

extern "C" void kernel_launch(void* const* d_in, const int* in_sizes, int n_in,
                              void* d_out, int out_size)
{
    const int*   trg     = (const int*)  d_in[0];
    const float* latent  = (const float*)d_in[3];
    const float* mems    = (const float*)d_in[4];
    const float* cmems   = (const float*)d_in[5];
    const float* pos_emb = (const float*)d_in[6];
    const float* embed   = (const float*)d_in[7];
    const float* W_self  = (const float*)d_in[8];
    const float* ln1_g   = (const float*)d_in[9];
    const float* ln1_b   = (const float*)d_in[10];
    const float* conv_w  = (const float*)d_in[11];
    const float* conv_b  = (const float*)d_in[12];
    const float* W_src   = (const float*)d_in[13];
    const float* ln2_g   = (const float*)d_in[14];
    const float* ln2_b   = (const float*)d_in[15];
    const float* w1      = (const float*)d_in[16];
    const float* b1      = (const float*)d_in[17];
    const float* w2      = (const float*)d_in[18];
    const float* b2      = (const float*)d_in[19];

    float* px    = dptr(g_x);     float* pa    = dptr(g_a);
    float* pkv   = dptr(g_kv);    float* pq    = dptr(g_q);
    float* pkvp  = dptr(g_kvp);
    float* pdots = dptr(g_dots);  float* ppd   = dptr(g_pd);
    float* pctx  = dptr(g_ctx);   float* ppackw= dptr(g_packw);
    float* pnewcm= dptr(g_newcm);
    float* ptb   = dptr(g_tb);    float* pcb   = dptr(g_cb);
    float* pd2   = dptr(g_d2);    float* pd3   = dptr(g_d3);
    float* pctxt = dptr(g_ctxt);  float* pctxc = dptr(g_ctxc);
    float* py    = dptr(g_y);     float* ph1   = dptr(g_h1);

    float* pk = pkvp;
    float* pv = pkvp + (long)B_*KV_*D_;
    float* pkt = ptb;
    float* pvt = ptb + (long)B_*MEM_*D_;
    float* pkc = pcb;
    float* pvc = pcb + (long)B_*CMEM_*D_;

    const int DD = D_ * D_;
    const int NX = B_*S_*D_;

    embed_k<<<(NX + 255)/256, 256>>>(trg, embed);
    zero_loss_k<<<1, 32>>>();

    for (int i = 0; i < NL_; i++) {
        const float* Wq  = W_self + (long)i*4*DD;
        const float* Wk  = Wq + DD;
        const float* Wo  = Wq + 3*DD;
        const float* Ws0 = W_src + (long)i*4*DD;
        const float* Ws1 = Ws0 + DD;
        const float* Ws3 = Ws0 + 3*DD;
        const float* mems_i  = mems  + (long)i*B_*MEM_*D_;
        const float* cmems_i = cmems + (long)i*B_*CMEM_*D_;
        const float* convw_i = conv_w + (long)i*DD*4;
        const float* convb_i = conv_b + (long)i*D_;
        const float* w1_i = w1 + (long)i*D_*FF_;
        const float* b1_i = b1 + (long)i*FF_;
        const float* w2_i = w2 + (long)i*FF_*D_;
        const float* b2_i = b2 + (long)i*D_;

        // ---- self attention over kv = [cmem, mem, x] ----
        concat_kv_k<<<(B_*KV_*D_ + 255)/256, 256>>>(cmems_i, mems_i);
        gF(false,128,false, px, Wq, pq, nullptr, nullptr, B_*S_, D_, D_, D_, D_, D_, 1.f);
        // K and V in one batched launch (Wk, Wv contiguous)
        gF(false,128,false, pkv, Wk, pk, nullptr, nullptr, B_*KV_, D_, D_, D_, D_, D_, 1.f,
           2, 1, 0, 0, DD, 0, (long)B_*KV_*D_, 0);
        gF(true,128,false, pq, pk, pdots, nullptr, nullptr, S_, KV_, DH_, D_, D_, KV_, 0.125f,
           B_*H_, H_, (long)S_*D_, 64, (long)KV_*D_, 64, (long)H_*S_*KV_, (long)S_*KV_);
        gF(true,128,false, pq, pos_emb, ppd, nullptr, nullptr, S_, KV_, DH_, D_, DH_, KV_, 8.f,
           B_*H_, H_, (long)S_*D_, 64, 0, (long)KV_*DH_, (long)H_*S_*KV_, (long)S_*KV_);
        softmax_pos_k<<<B_*H_*S_, 256>>>();
        gF(false,64,false, pdots, pv, pctx, nullptr, nullptr, S_, DH_, KV_, KV_, D_, D_, 1.f,
           B_*H_, H_, (long)H_*S_*KV_, (long)S_*KV_, (long)KV_*D_, 64, (long)S_*D_, 64);
        gF(false,128,false, pctx, Wo, pa, nullptr, nullptr, B_*S_, D_, D_, D_, D_, D_, 1.f);
        ln_k<<<B_*S_, 256>>>(pa, px, px, ln1_g + (long)i*D_, ln1_b + (long)i*D_);

        // ---- conv compress ----
        pack_convw_k<<<((4*D_)*D_ + 255)/256, 256>>>(convw_i);
        gF(false,128,false, mems_i, ppackw, pnewcm, convb_i, nullptr, B_*CMEM_, D_, 4*D_, 4*D_, D_, D_, 1.f);

        // ---- reconstruction attentions (loss) ----
        gF(false,128,false, px, Wq, pq, nullptr, nullptr, B_*S_, D_, D_, D_, D_, D_, 1.f);
        gF(false,128,false, mems_i, Wk, pkt, nullptr, nullptr, B_*MEM_, D_, D_, D_, D_, D_, 1.f,
           2, 1, 0, 0, DD, 0, (long)B_*MEM_*D_, 0);
        gF(true,128,false, pq, pkt, pd2, nullptr, nullptr, S_, MEM_, DH_, D_, D_, MEM_, 0.125f,
           B_*H_, H_, (long)S_*D_, 64, (long)MEM_*D_, 64, (long)H_*S_*MEM_, (long)S_*MEM_);
        softmax_k<<<B_*H_*S_, 256>>>(pd2, MEM_);
        gF(false,64,false, pd2, pvt, pctxt, nullptr, nullptr, S_, DH_, MEM_, MEM_, D_, D_, 1.f,
           B_*H_, H_, (long)H_*S_*MEM_, (long)S_*MEM_, (long)MEM_*D_, 64, (long)S_*D_, 64);
        gF(false,128,false, pnewcm, Wk, pkc, nullptr, nullptr, B_*CMEM_, D_, D_, D_, D_, D_, 1.f,
           2, 1, 0, 0, DD, 0, (long)B_*CMEM_*D_, 0);
        gF(true,128,false, pq, pkc, pd3, nullptr, nullptr, S_, CMEM_, DH_, D_, D_, CMEM_, 0.125f,
           B_*H_, H_, (long)S_*D_, 64, (long)CMEM_*D_, 64, (long)H_*S_*CMEM_, (long)S_*CMEM_);
        softmax_k<<<B_*H_*S_, 256>>>(pd3, CMEM_);
        gF(false,64,false, pd3, pvc, pctxc, nullptr, nullptr, S_, DH_, CMEM_, CMEM_, D_, D_, 1.f,
           B_*H_, H_, (long)H_*S_*CMEM_, (long)S_*CMEM_, (long)CMEM_*D_, 64, (long)S_*D_, 64);
        sse_k<<<1024, 256>>>(pctxc, pctxt, NX);

        // ---- cross attention to latent (output REPLACES x) ----
        gF(false,128,false, px, Ws0, pq, nullptr, nullptr, B_*S_, D_, D_, D_, D_, D_, 1.f);
        gF(false,128,false, latent, Ws1, pkt, nullptr, nullptr, B_*LLAT_, D_, D_, D_, D_, D_, 1.f,
           2, 1, 0, 0, DD, 0, (long)B_*MEM_*D_, 0);
        gF(true,128,false, pq, pkt, pd2, nullptr, nullptr, S_, LLAT_, DH_, D_, D_, LLAT_, 0.125f,
           B_*H_, H_, (long)S_*D_, 64, (long)LLAT_*D_, 64, (long)H_*S_*LLAT_, (long)S_*LLAT_);
        softmax_k<<<B_*H_*S_, 256>>>(pd2, LLAT_);
        gF(false,64,false, pd2, pvt, pctx, nullptr, nullptr, S_, DH_, LLAT_, LLAT_, D_, D_, 1.f,
           B_*H_, H_, (long)H_*S_*LLAT_, (long)S_*LLAT_, (long)LLAT_*D_, 64, (long)S_*D_, 64);
        gF(false,128,false, pctx, Ws3, pa, nullptr, nullptr, B_*S_, D_, D_, D_, D_, D_, 1.f);

        // ---- FFN: x = a + gelu(LN(a) @ w1 + b1) @ w2 + b2 ----
        ln_k<<<B_*S_, 256>>>(pa, nullptr, py, ln2_g + (long)i*D_, ln2_b + (long)i*D_);
        gF(false,128,true,  py, w1_i, ph1, b1_i, nullptr, B_*S_, FF_, D_, D_, FF_, FF_, 1.f);
        gF(false,128,false, ph1, w2_i, px, b2_i, pa, B_*S_, D_, FF_, FF_, D_, D_, 1.f);
    }

    finalize_k<<<(out_size + 255)/256, 256>>>((float*)d_out, out_size);
}

// round 4
// speedup vs baseline: 1.2263x; 1.1319x over previous
#include <cuda_runtime.h>
#include <math.h>
#include <stdint.h>

#define B_    4
#define S_    512
#define D_    512
#define H_    8
#define DH_   64
#define MEM_  512
#define CMEM_ 128
#define KV_   1152
#define LLAT_ 256
#define FF_   2048
#define NL_   4

// ------------------------- scratch (device globals) -------------------------
__device__ float g_x   [B_*S_*D_];
__device__ float g_a   [B_*S_*D_];
__device__ float g_kv  [B_*KV_*D_];
__device__ float g_q   [B_*S_*D_];
__device__ float g_kvp [2*B_*KV_*D_];
__device__ float g_dots[B_*H_*S_*KV_];
__device__ float g_pd  [B_*H_*S_*KV_];
__device__ float g_ctx [B_*S_*D_];
__device__ float g_packw[(4*D_)*D_];
__device__ float g_newcm[B_*CMEM_*D_];
__device__ float g_tb  [2*B_*MEM_*D_];
__device__ float g_cb  [2*B_*CMEM_*D_];
__device__ float g_d2  [B_*H_*S_*MEM_];
__device__ float g_d3  [B_*H_*S_*CMEM_];
__device__ float g_ctxt[B_*S_*D_];
__device__ float g_ctxc[B_*S_*D_];
__device__ float g_y   [B_*S_*D_];
__device__ float g_h1  [B_*S_*FF_];
__device__ float g_loss[1];

// ------------------------- TF32 helpers -------------------------------------
__device__ __forceinline__ uint32_t f2tf(float x) {
    uint32_t r;
    asm("cvt.rna.tf32.f32 %0, %1;" : "=r"(r) : "f"(x));
    return r;
}

__device__ __forceinline__ void mma8(float c[4], const uint32_t a[4], const uint32_t b[2]) {
    asm volatile(
        "mma.sync.aligned.m16n8k8.row.col.f32.tf32.tf32.f32 "
        "{%0,%1,%2,%3},{%4,%5,%6,%7},{%8,%9},{%0,%1,%2,%3};\n"
        : "+f"(c[0]), "+f"(c[1]), "+f"(c[2]), "+f"(c[3])
        : "r"(a[0]), "r"(a[1]), "r"(a[2]), "r"(a[3]), "r"(b[0]), "r"(b[1]));
}

// ------------------------- 3xTF32 tensor-core GEMM --------------------------
// C = alpha * A @ op(B) [+bias] [GELU] [+Res], op = B^T if TB.
// Block tile 64x64, BK=32, 128 threads (4 warps, 2x2 of 32x32).
// Requires M%64==0, N%64==0, K%32==0, lda/ldb/ldc %4==0, 16B-aligned bases.
// Batched via blockIdx.z: bi=z/Hdiv, hi=z%Hdiv.
#define SST 36   // smem row stride (floats): (4*group + tig) covers 32 banks
template<bool TB, bool GELU>
__global__ void __launch_bounds__(128) gemm_t(
    const float* __restrict__ A, const float* __restrict__ Bm,
    float* __restrict__ C, const float* __restrict__ bias,
    const float* __restrict__ Res,
    int K, int lda, int ldb, int ldc, float alpha,
    int Hdiv, long sAb, long sAh, long sBb, long sBh, long sCb, long sCh)
{
    const int z  = blockIdx.z;
    const int bi = z / Hdiv, hi = z - bi * Hdiv;
    A  += (long)bi*sAb + (long)hi*sAh;
    Bm += (long)bi*sBb + (long)hi*sBh;
    C  += (long)bi*sCb + (long)hi*sCh;

    const int m0 = blockIdx.y * 64;
    const int n0 = blockIdx.x * 64;

    // [hi/lo][row][col]; A rows = m, B rows = n (both k-contiguous inside)
    __shared__ float As[2][64][SST];
    __shared__ float Bs[2][64][SST];

    const int t    = threadIdx.x;
    const int warp = t >> 5;
    const int lane = t & 31;
    const int wm = (warp & 1) * 32;
    const int wn = (warp >> 1) * 32;
    const int group = lane >> 2;
    const int tig   = lane & 3;

    float c[2][4][4];
#pragma unroll
    for (int mt = 0; mt < 2; mt++)
#pragma unroll
        for (int nt = 0; nt < 4; nt++)
#pragma unroll
            for (int r = 0; r < 4; r++) c[mt][nt][r] = 0.f;

    for (int k0 = 0; k0 < K; k0 += 32) {
        // ---- load A tile 64x32 (row-major, k contiguous) ----
#pragma unroll
        for (int p = 0; p < 4; p++) {
            const int m = (t >> 3) + p * 16;
            const int k = (t & 7) << 2;
            float4 v = *(const float4*)(A + (long)(m0 + m) * lda + k0 + k);
            uint32_t hx = f2tf(v.x), hy = f2tf(v.y), hz = f2tf(v.z), hw = f2tf(v.w);
            As[0][m][k+0] = __uint_as_float(hx);
            As[0][m][k+1] = __uint_as_float(hy);
            As[0][m][k+2] = __uint_as_float(hz);
            As[0][m][k+3] = __uint_as_float(hw);
            As[1][m][k+0] = __uint_as_float(f2tf(v.x - __uint_as_float(hx)));
            As[1][m][k+1] = __uint_as_float(f2tf(v.y - __uint_as_float(hy)));
            As[1][m][k+2] = __uint_as_float(f2tf(v.z - __uint_as_float(hz)));
            As[1][m][k+3] = __uint_as_float(f2tf(v.w - __uint_as_float(hw)));
        }
        // ---- load B tile -> Bs[n][k] ----
        if (TB) {
            // B is [N,K] row-major: same pattern as A
#pragma unroll
            for (int p = 0; p < 4; p++) {
                const int n = (t >> 3) + p * 16;
                const int k = (t & 7) << 2;
                float4 v = *(const float4*)(Bm + (long)(n0 + n) * ldb + k0 + k);
                uint32_t hx = f2tf(v.x), hy = f2tf(v.y), hz = f2tf(v.z), hw = f2tf(v.w);
                Bs[0][n][k+0] = __uint_as_float(hx);
                Bs[0][n][k+1] = __uint_as_float(hy);
                Bs[0][n][k+2] = __uint_as_float(hz);
                Bs[0][n][k+3] = __uint_as_float(hw);
                Bs[1][n][k+0] = __uint_as_float(f2tf(v.x - __uint_as_float(hx)));
                Bs[1][n][k+1] = __uint_as_float(f2tf(v.y - __uint_as_float(hy)));
                Bs[1][n][k+2] = __uint_as_float(f2tf(v.z - __uint_as_float(hz)));
                Bs[1][n][k+3] = __uint_as_float(f2tf(v.w - __uint_as_float(hw)));
            }
        } else {
            // B is [K,N] row-major: read coalesced along N, transpose into Bs
#pragma unroll
            for (int p = 0; p < 4; p++) {
                const int k = (t >> 4) + p * 8;
                const int n = (t & 15) << 2;
                float4 v = *(const float4*)(Bm + (long)(k0 + k) * ldb + n0 + n);
                uint32_t hx = f2tf(v.x), hy = f2tf(v.y), hz = f2tf(v.z), hw = f2tf(v.w);
                Bs[0][n+0][k] = __uint_as_float(hx);
                Bs[0][n+1][k] = __uint_as_float(hy);
                Bs[0][n+2][k] = __uint_as_float(hz);
                Bs[0][n+3][k] = __uint_as_float(hw);
                Bs[1][n+0][k] = __uint_as_float(f2tf(v.x - __uint_as_float(hx)));
                Bs[1][n+1][k] = __uint_as_float(f2tf(v.y - __uint_as_float(hy)));
                Bs[1][n+2][k] = __uint_as_float(f2tf(v.z - __uint_as_float(hz)));
                Bs[1][n+3][k] = __uint_as_float(f2tf(v.w - __uint_as_float(hw)));
            }
        }
        __syncthreads();

#pragma unroll
        for (int kk = 0; kk < 32; kk += 8) {
            uint32_t ah[2][4], al[2][4], bh[4][2], bl[4][2];
#pragma unroll
            for (int mt = 0; mt < 2; mt++) {
                const int r0 = wm + mt * 16 + group;
                ah[mt][0] = __float_as_uint(As[0][r0    ][kk + tig]);
                ah[mt][1] = __float_as_uint(As[0][r0 + 8][kk + tig]);
                ah[mt][2] = __float_as_uint(As[0][r0    ][kk + tig + 4]);
                ah[mt][3] = __float_as_uint(As[0][r0 + 8][kk + tig + 4]);
                al[mt][0] = __float_as_uint(As[1][r0    ][kk + tig]);
                al[mt][1] = __float_as_uint(As[1][r0 + 8][kk + tig]);
                al[mt][2] = __float_as_uint(As[1][r0    ][kk + tig + 4]);
                al[mt][3] = __float_as_uint(As[1][r0 + 8][kk + tig + 4]);
            }
#pragma unroll
            for (int nt = 0; nt < 4; nt++) {
                const int nr = wn + nt * 8 + group;
                bh[nt][0] = __float_as_uint(Bs[0][nr][kk + tig]);
                bh[nt][1] = __float_as_uint(Bs[0][nr][kk + tig + 4]);
                bl[nt][0] = __float_as_uint(Bs[1][nr][kk + tig]);
                bl[nt][1] = __float_as_uint(Bs[1][nr][kk + tig + 4]);
            }
#pragma unroll
            for (int mt = 0; mt < 2; mt++)
#pragma unroll
                for (int nt = 0; nt < 4; nt++) {
                    mma8(c[mt][nt], al[mt], bh[nt]);
                    mma8(c[mt][nt], ah[mt], bl[nt]);
                    mma8(c[mt][nt], ah[mt], bh[nt]);
                }
        }
        __syncthreads();
    }

    // ---- epilogue ----
#pragma unroll
    for (int mt = 0; mt < 2; mt++) {
#pragma unroll
        for (int half = 0; half < 2; half++) {
            const int gm = m0 + wm + mt * 16 + group + half * 8;
            float* crow = C + (long)gm * ldc;
            const float* rrow = Res ? (Res + (long)gm * ldc) : nullptr;
#pragma unroll
            for (int nt = 0; nt < 4; nt++) {
                const int gn = n0 + wn + nt * 8 + 2 * tig;
                float v0 = alpha * c[mt][nt][half * 2 + 0];
                float v1 = alpha * c[mt][nt][half * 2 + 1];
                if (bias) {
                    float2 bv = *(const float2*)&bias[gn];
                    v0 += bv.x; v1 += bv.y;
                }
                if (GELU) {
                    v0 = 0.5f * v0 * (1.f + erff(v0 * 0.70710678118654752f));
                    v1 = 0.5f * v1 * (1.f + erff(v1 * 0.70710678118654752f));
                }
                if (rrow) {
                    float2 rv = *(const float2*)&rrow[gn];
                    v0 += rv.x; v1 += rv.y;
                }
                float2 o = make_float2(v0, v1);
                *(float2*)&crow[gn] = o;
            }
        }
    }
}

// ------------------------- elementwise / reduction kernels ------------------
__global__ void embed_k(const int* __restrict__ trg, const float* __restrict__ embed)
{
    int idx = blockIdx.x * blockDim.x + threadIdx.x;
    if (idx >= B_*S_*D_) return;
    int row = idx / D_;
    g_x[idx] = embed[(long)trg[row]*D_ + (idx % D_)];
}

__global__ void concat_kv_k(const float* __restrict__ cm, const float* __restrict__ m)
{
    int idx = blockIdx.x * blockDim.x + threadIdx.x;
    if (idx >= B_*KV_*D_) return;
    int d = idx % D_;
    int j = (idx / D_) % KV_;
    int b = idx / (D_*KV_);
    float v;
    if (j < CMEM_)             v = cm [((long)b*CMEM_ + j)*D_ + d];
    else if (j < CMEM_ + MEM_) v = m  [((long)b*MEM_ + (j - CMEM_))*D_ + d];
    else                       v = g_x[((long)b*S_  + (j - CMEM_ - MEM_))*D_ + d];
    g_kv[idx] = v;
}

__global__ void softmax_pos_k()
{
    const long row = blockIdx.x;
    const int  q   = (int)(row % S_);
    float* dp = g_dots + row * (long)KV_;
    const float* pp = g_pd + row * (long)KV_;
    const int t = threadIdx.x;

    float v[5];
    float m = -1e30f;
#pragma unroll
    for (int r = 0; r < 5; r++) {
        int i = t + 256*r;
        if (i < KV_) {
            float val = dp[i];
            int p = i - q + (S_ - 1);
            if (p < KV_) val += pp[p];
            v[r] = val;
            m = fmaxf(m, val);
        } else v[r] = -1e30f;
    }
    __shared__ float red[256];
    red[t] = m; __syncthreads();
    for (int st = 128; st > 0; st >>= 1) { if (t < st) red[t] = fmaxf(red[t], red[t+st]); __syncthreads(); }
    m = red[0]; __syncthreads();
    float s = 0.f;
#pragma unroll
    for (int r = 0; r < 5; r++) {
        int i = t + 256*r;
        if (i < KV_) { v[r] = expf(v[r] - m); s += v[r]; }
    }
    red[t] = s; __syncthreads();
    for (int st = 128; st > 0; st >>= 1) { if (t < st) red[t] += red[t+st]; __syncthreads(); }
    float inv = 1.f / red[0];
#pragma unroll
    for (int r = 0; r < 5; r++) {
        int i = t + 256*r;
        if (i < KV_) dp[i] = v[r] * inv;
    }
}

__global__ void softmax_k(float* __restrict__ d, int L)
{
    long row = blockIdx.x;
    float* p = d + row * (long)L;
    const int t = threadIdx.x;
    float v[5];
    float m = -1e30f;
    const int nr = (L + 255) >> 8;
    for (int r = 0; r < nr; r++) {
        int i = t + 256*r;
        v[r] = (i < L) ? p[i] : -1e30f;
        m = fmaxf(m, v[r]);
    }
    __shared__ float red[256];
    red[t] = m; __syncthreads();
    for (int st = 128; st > 0; st >>= 1) { if (t < st) red[t] = fmaxf(red[t], red[t+st]); __syncthreads(); }
    m = red[0]; __syncthreads();
    float s = 0.f;
    for (int r = 0; r < nr; r++) {
        int i = t + 256*r;
        if (i < L) { v[r] = expf(v[r] - m); s += v[r]; }
    }
    red[t] = s; __syncthreads();
    for (int st = 128; st > 0; st >>= 1) { if (t < st) red[t] += red[t+st]; __syncthreads(); }
    float inv = 1.f / red[0];
    for (int r = 0; r < nr; r++) {
        int i = t + 256*r;
        if (i < L) p[i] = v[r] * inv;
    }
}

__global__ void ln_k(const float* __restrict__ in, const float* __restrict__ res,
                     float* __restrict__ out, const float* __restrict__ g,
                     const float* __restrict__ bta)
{
    long row = blockIdx.x;
    const float* p = in + row * D_;
    int t = threadIdx.x;
    float v0 = p[t]       + (res ? res[row*D_ + t]       : 0.f);
    float v1 = p[t + 256] + (res ? res[row*D_ + t + 256] : 0.f);
    __shared__ float s1[256], s2[256];
    s1[t] = v0 + v1; s2[t] = v0*v0 + v1*v1;
    __syncthreads();
    for (int st = 128; st > 0; st >>= 1) { if (t < st) { s1[t] += s1[t+st]; s2[t] += s2[t+st]; } __syncthreads(); }
    float mu  = s1[0] * (1.f / D_);
    float var = s2[0] * (1.f / D_) - mu*mu;
    float inv = rsqrtf(var + 1e-5f);
    out[row*D_ + t]       = (v0 - mu) * inv * g[t]       + bta[t];
    out[row*D_ + t + 256] = (v1 - mu) * inv * g[t + 256] + bta[t + 256];
}

__global__ void pack_convw_k(const float* __restrict__ w)
{
    int idx = blockIdx.x * blockDim.x + threadIdx.x;
    if (idx >= (4*D_)*D_) return;
    int o = idx % D_;
    int kap = idx / D_;
    int r = kap / D_, d = kap % D_;
    g_packw[(long)kap*D_ + o] = w[(long)o*(D_*4) + d*4 + r];
}

__global__ void zero_loss_k() { if (threadIdx.x == 0 && blockIdx.x == 0) g_loss[0] = 0.f; }

__global__ void sse_k(const float* __restrict__ a, const float* __restrict__ b, int n)
{
    __shared__ float red[256];
    int t = threadIdx.x;
    float s = 0.f;
    for (int i = blockIdx.x * 256 + t; i < n; i += gridDim.x * 256) {
        float d = a[i] - b[i];
        s += d * d;
    }
    red[t] = s; __syncthreads();
    for (int st = 128; st > 0; st >>= 1) { if (t < st) red[t] += red[t+st]; __syncthreads(); }
    if (t == 0) atomicAdd(&g_loss[0], red[0]);
}

__global__ void finalize_k(float* __restrict__ out, int out_size)
{
    int idx = blockIdx.x * blockDim.x + threadIdx.x;
    if (idx >= out_size) return;
    const int n = B_*S_*D_;
    if (idx < n) out[idx] = g_x[idx];
    else         out[idx] = g_loss[0] * (1.f / ((float)n * (float)NL_));
}

// ------------------------------- host driver --------------------------------
static void gT(bool tb, bool gelu,
               const float* A, const float* Bm, float* C, const float* bias,
               const float* Res, int M, int N, int K,
               int lda, int ldb, int ldc, float alpha,
               int batch = 1, int Hdiv = 1,
               long sAb = 0, long sAh = 0, long sBb = 0, long sBh = 0,
               long sCb = 0, long sCh = 0)
{
    dim3 g(N / 64, M / 64, batch);
    if (tb)
        gemm_t<true,false><<<g,128>>>(A,Bm,C,bias,Res,K,lda,ldb,ldc,alpha,Hdiv,sAb,sAh,sBb,sBh,sCb,sCh);
    else if (gelu)
        gemm_t<false,true><<<g,128>>>(A,Bm,C,bias,Res,K,lda,ldb,ldc,alpha,Hdiv,sAb,sAh,sBb,sBh,sCb,sCh);
    else
        gemm_t<false,false><<<g,128>>>(A,Bm,C,bias,Res,K,lda,ldb,ldc,alpha,Hdiv,sAb,sAh,sBb,sBh,sCb,sCh);
}

static float* dptr(const void* sym) { void* p = nullptr; cudaGetSymbolAddress(&p, sym); return (float*)p; }

extern "C" void kernel_launch(void* const* d_in, const int* in_sizes, int n_in,
                              void* d_out, int out_size)
{
    const int*   trg     = (const int*)  d_in[0];
    const float* latent  = (const float*)d_in[3];
    const float* mems    = (const float*)d_in[4];
    const float* cmems   = (const float*)d_in[5];
    const float* pos_emb = (const float*)d_in[6];
    const float* embed   = (const float*)d_in[7];
    const float* W_self  = (const float*)d_in[8];
    const float* ln1_g   = (const float*)d_in[9];
    const float* ln1_b   = (const float*)d_in[10];
    const float* conv_w  = (const float*)d_in[11];
    const float* conv_b  = (const float*)d_in[12];
    const float* W_src   = (const float*)d_in[13];
    const float* ln2_g   = (const float*)d_in[14];
    const float* ln2_b   = (const float*)d_in[15];
    const float* w1      = (const float*)d_in[16];
    const float* b1      = (const float*)d_in[17];
    const float* w2      = (const float*)d_in[18];
    const float* b2      = (const float*)d_in[19];

    float* px    = dptr(g_x);     float* pa    = dptr(g_a);
    float* pkv   = dptr(g_kv);    float* pq    = dptr(g_q);
    float* pkvp  = dptr(g_kvp);
    float* pdots = dptr(g_dots);  float* ppd   = dptr(g_pd);
    float* pctx  = dptr(g_ctx);   float* ppackw= dptr(g_packw);
    float* pnewcm= dptr(g_newcm);
    float* ptb   = dptr(g_tb);    float* pcb   = dptr(g_cb);
    float* pd2   = dptr(g_d2);    float* pd3   = dptr(g_d3);
    float* pctxt = dptr(g_ctxt);  float* pctxc = dptr(g_ctxc);
    float* py    = dptr(g_y);     float* ph1   = dptr(g_h1);

    float* pk = pkvp;
    float* pv = pkvp + (long)B_*KV_*D_;
    float* pkt = ptb;
    float* pvt = ptb + (long)B_*MEM_*D_;
    float* pkc = pcb;
    float* pvc = pcb + (long)B_*CMEM_*D_;

    const int DD = D_ * D_;
    const int NX = B_*S_*D_;

    embed_k<<<(NX + 255)/256, 256>>>(trg, embed);
    zero_loss_k<<<1, 32>>>();

    for (int i = 0; i < NL_; i++) {
        const float* Wq  = W_self + (long)i*4*DD;
        const float* Wk  = Wq + DD;
        const float* Wo  = Wq + 3*DD;
        const float* Ws0 = W_src + (long)i*4*DD;
        const float* Ws1 = Ws0 + DD;
        const float* Ws3 = Ws0 + 3*DD;
        const float* mems_i  = mems  + (long)i*B_*MEM_*D_;
        const float* cmems_i = cmems + (long)i*B_*CMEM_*D_;
        const float* convw_i = conv_w + (long)i*DD*4;
        const float* convb_i = conv_b + (long)i*D_;
        const float* w1_i = w1 + (long)i*D_*FF_;
        const float* b1_i = b1 + (long)i*FF_;
        const float* w2_i = w2 + (long)i*FF_*D_;
        const float* b2_i = b2 + (long)i*D_;

        // ---- self attention over kv = [cmem, mem, x] ----
        concat_kv_k<<<(B_*KV_*D_ + 255)/256, 256>>>(cmems_i, mems_i);
        gT(false,false, px, Wq, pq, nullptr, nullptr, B_*S_, D_, D_, D_, D_, D_, 1.f);
        gT(false,false, pkv, Wk, pk, nullptr, nullptr, B_*KV_, D_, D_, D_, D_, D_, 1.f,
           2, 1, 0, 0, DD, 0, (long)B_*KV_*D_, 0);
        gT(true,false, pq, pk, pdots, nullptr, nullptr, S_, KV_, DH_, D_, D_, KV_, 0.125f,
           B_*H_, H_, (long)S_*D_, 64, (long)KV_*D_, 64, (long)H_*S_*KV_, (long)S_*KV_);
        gT(true,false, pq, pos_emb, ppd, nullptr, nullptr, S_, KV_, DH_, D_, DH_, KV_, 8.f,
           B_*H_, H_, (long)S_*D_, 64, 0, (long)KV_*DH_, (long)H_*S_*KV_, (long)S_*KV_);
        softmax_pos_k<<<B_*H_*S_, 256>>>();
        gT(false,false, pdots, pv, pctx, nullptr, nullptr, S_, DH_, KV_, KV_, D_, D_, 1.f,
           B_*H_, H_, (long)H_*S_*KV_, (long)S_*KV_, (long)KV_*D_, 64, (long)S_*D_, 64);
        gT(false,false, pctx, Wo, pa, nullptr, nullptr, B_*S_, D_, D_, D_, D_, D_, 1.f);
        ln_k<<<B_*S_, 256>>>(pa, px, px, ln1_g + (long)i*D_, ln1_b + (long)i*D_);

        // ---- conv compress ----
        pack_convw_k<<<((4*D_)*D_ + 255)/256, 256>>>(convw_i);
        gT(false,false, mems_i, ppackw, pnewcm, convb_i, nullptr, B_*CMEM_, D_, 4*D_, 4*D_, D_, D_, 1.f);

        // ---- reconstruction attentions (loss) ----
        gT(false,false, px, Wq, pq, nullptr, nullptr, B_*S_, D_, D_, D_, D_, D_, 1.f);
        gT(false,false, mems_i, Wk, pkt, nullptr, nullptr, B_*MEM_, D_, D_, D_, D_, D_, 1.f,
           2, 1, 0, 0, DD, 0, (long)B_*MEM_*D_, 0);
        gT(true,false, pq, pkt, pd2, nullptr, nullptr, S_, MEM_, DH_, D_, D_, MEM_, 0.125f,
           B_*H_, H_, (long)S_*D_, 64, (long)MEM_*D_, 64, (long)H_*S_*MEM_, (long)S_*MEM_);
        softmax_k<<<B_*H_*S_, 256>>>(pd2, MEM_);
        gT(false,false, pd2, pvt, pctxt, nullptr, nullptr, S_, DH_, MEM_, MEM_, D_, D_, 1.f,
           B_*H_, H_, (long)H_*S_*MEM_, (long)S_*MEM_, (long)MEM_*D_, 64, (long)S_*D_, 64);
        gT(false,false, pnewcm, Wk, pkc, nullptr, nullptr, B_*CMEM_, D_, D_, D_, D_, D_, 1.f,
           2, 1, 0, 0, DD, 0, (long)B_*CMEM_*D_, 0);
        gT(true,false, pq, pkc, pd3, nullptr, nullptr, S_, CMEM_, DH_, D_, D_, CMEM_, 0.125f,
           B_*H_, H_, (long)S_*D_, 64, (long)CMEM_*D_, 64, (long)H_*S_*CMEM_, (long)S_*CMEM_);
        softmax_k<<<B_*H_*S_, 256>>>(pd3, CMEM_);
        gT(false,false, pd3, pvc, pctxc, nullptr, nullptr, S_, DH_, CMEM_, CMEM_, D_, D_, 1.f,
           B_*H_, H_, (long)H_*S_*CMEM_, (long)S_*CMEM_, (long)CMEM_*D_, 64, (long)S_*D_, 64);
        sse_k<<<1024, 256>>>(pctxc, pctxt, NX);

        // ---- cross attention to latent (output REPLACES x) ----
        gT(false,false, px,     Ws0, pq,  nullptr, nullptr, B_*S_, D_, D_, D_, D_, D_, 1.f);
        gT(false,false, latent, Ws1, pkt, nullptr, nullptr, B_*LLAT_, D_, D_, D_, D_, D_, 1.f,
           2, 1, 0, 0, DD, 0, (long)B_*MEM_*D_, 0);
        gT(true,false, pq, pkt, pd2, nullptr, nullptr, S_, LLAT_, DH_, D_, D_, LLAT_, 0.125f,
           B_*H_, H_, (long)S_*D_, 64, (long)LLAT_*D_, 64, (long)H_*S_*LLAT_, (long)S_*LLAT_);
        softmax_k<<<B_*H_*S_, 256>>>(pd2, LLAT_);
        gT(false,false, pd2, pvt, pctx, nullptr, nullptr, S_, DH_, LLAT_, LLAT_, D_, D_, 1.f,
           B_*H_, H_, (long)H_*S_*LLAT_, (long)S_*LLAT_, (long)LLAT_*D_, 64, (long)S_*D_, 64);
        gT(false,false, pctx, Ws3, pa, nullptr, nullptr, B_*S_, D_, D_, D_, D_, D_, 1.f);

        // ---- FFN: x = a + gelu(LN(a) @ w1 + b1) @ w2 + b2 ----
        ln_k<<<B_*S_, 256>>>(pa, nullptr, py, ln2_g + (long)i*D_, ln2_b + (long)i*D_);
        gT(false,true,  py, w1_i, ph1, b1_i, nullptr, B_*S_, FF_, D_, D_, FF_, FF_, 1.f);
        gT(false,false, ph1, w2_i, px, b2_i, pa, B_*S_, D_, FF_, FF_, D_, D_, 1.f);
    }

    finalize_k<<<(out_size + 255)/256, 256>>>((float*)d_out, out_size);
}